// round 16
// baseline (speedup 1.0000x reference)
#include <cuda_runtime.h>
#include <cstdint>

// HomographyNet via Cayley-Hamilton.
// C = [ v4   v2   v0 ]      (traceless, sl(3))
//     [ v3  -v4-v5 v1 ]
//     [ v6   v7   v5 ]
// C^3 = p*C + q*I,  p = tr(C^2)/2,  q = det(C)
// => sum_{i=0..9} C^i/i! = a(p,q)*I + b(p,q)*C + c(p,q)*C^2   (exact degree-9 expansion)
//
// Memory: traffic is mandatory (64MB in + 72MB out, fp32) and the chip-level
// wall is the LTS cap (path-independent), so no cache hints. This round cuts
// LSU issue with 256-bit ld/st.global.v8.b32 (sm_100+): 1 load per item,
// 32B-granular warp-coalesced drain stores.

__device__ __forceinline__ void expm3x3_ch(const float vv[8], float H[9]) {
    const float c00 = vv[4], c01 = vv[2], c02 = vv[0];
    const float c10 = vv[3], c11 = -vv[4] - vv[5], c12 = vv[1];
    const float c20 = vv[6], c21 = vv[7], c22 = vv[5];

    // D = C^2
    const float d00 = fmaf(c02, c20, fmaf(c01, c10, c00 * c00));
    const float d01 = fmaf(c02, c21, fmaf(c01, c11, c00 * c01));
    const float d02 = fmaf(c02, c22, fmaf(c01, c12, c00 * c02));
    const float d10 = fmaf(c12, c20, fmaf(c11, c10, c10 * c00));
    const float d11 = fmaf(c12, c21, fmaf(c11, c11, c10 * c01));
    const float d12 = fmaf(c12, c22, fmaf(c11, c12, c10 * c02));
    const float d20 = fmaf(c22, c20, fmaf(c21, c10, c20 * c00));
    const float d21 = fmaf(c22, c21, fmaf(c21, c11, c20 * c01));
    const float d22 = fmaf(c22, c22, fmaf(c21, c12, c20 * c02));

    // invariants
    const float p = 0.5f * (d00 + d11 + d22);          // tr(C^2)/2
    const float q = fmaf(c00, fmaf(c11, c22, -c12 * c21),
                   fmaf(-c01, fmaf(c10, c22, -c12 * c20),
                         c02 * fmaf(c10, c21, -c11 * c20)));  // det(C)

    // monomials
    const float p2  = p * p;
    const float q2  = q * q;
    const float pq  = p * q;
    const float p3  = p2 * p;
    const float p4  = p2 * p2;
    const float q3  = q * q2;
    const float p2q = p2 * q;
    const float pq2 = p * q2;
    const float p3q = p3 * q;

    float a = 1.0f;
    a = fmaf(q,   1.0f / 6.0f,      a);
    a = fmaf(pq,  1.0f / 120.0f,    a);
    a = fmaf(q2,  1.0f / 720.0f,    a);
    a = fmaf(p2q, 1.0f / 5040.0f,   a);
    a = fmaf(pq2, 1.0f / 20160.0f,  a);
    a = fmaf(q3,  1.0f / 362880.0f, a);
    a = fmaf(p3q, 1.0f / 362880.0f, a);

    float b = 1.0f;
    b = fmaf(p,   1.0f / 6.0f,      b);
    b = fmaf(q,   1.0f / 24.0f,     b);
    b = fmaf(p2,  1.0f / 120.0f,    b);
    b = fmaf(pq,  1.0f / 360.0f,    b);
    b = fmaf(q2,  1.0f / 5040.0f,   b);
    b = fmaf(p3,  1.0f / 5040.0f,   b);
    b = fmaf(p2q, 1.0f / 13440.0f,  b);
    b = fmaf(pq2, 1.0f / 120960.0f, b);
    b = fmaf(p4,  1.0f / 362880.0f, b);

    float c = 0.5f;
    c = fmaf(p,   1.0f / 24.0f,     c);
    c = fmaf(q,   1.0f / 120.0f,    c);
    c = fmaf(p2,  1.0f / 720.0f,    c);
    c = fmaf(pq,  1.0f / 2520.0f,   c);
    c = fmaf(q2,  1.0f / 40320.0f,  c);
    c = fmaf(p3,  1.0f / 40320.0f,  c);
    c = fmaf(p2q, 1.0f / 120960.0f, c);

    // H = a*I + b*C + c*C^2
    H[0] = fmaf(b, c00, fmaf(c, d00, a));
    H[1] = fmaf(b, c01, c * d01);
    H[2] = fmaf(b, c02, c * d02);
    H[3] = fmaf(b, c10, c * d10);
    H[4] = fmaf(b, c11, fmaf(c, d11, a));
    H[5] = fmaf(b, c12, c * d12);
    H[6] = fmaf(b, c20, c * d20);
    H[7] = fmaf(b, c21, c * d21);
    H[8] = fmaf(b, c22, fmaf(c, d22, a));
}

// 256-bit global load (streaming): one item's 8 floats in one instruction.
__device__ __forceinline__ void ldg256_cs(const float* p, float* v) {
    uint32_t r0, r1, r2, r3, r4, r5, r6, r7;
    asm volatile("ld.global.cs.v8.b32 {%0,%1,%2,%3,%4,%5,%6,%7}, [%8];"
                 : "=r"(r0), "=r"(r1), "=r"(r2), "=r"(r3),
                   "=r"(r4), "=r"(r5), "=r"(r6), "=r"(r7)
                 : "l"(p));
    v[0] = __uint_as_float(r0); v[1] = __uint_as_float(r1);
    v[2] = __uint_as_float(r2); v[3] = __uint_as_float(r3);
    v[4] = __uint_as_float(r4); v[5] = __uint_as_float(r5);
    v[6] = __uint_as_float(r6); v[7] = __uint_as_float(r7);
}

// 256-bit global store (streaming) from two float4s.
__device__ __forceinline__ void stg256_cs(float* p, float4 x0, float4 x1) {
    asm volatile("st.global.cs.v8.b32 [%0], {%1,%2,%3,%4,%5,%6,%7,%8};"
                 :: "l"(p),
                    "r"(__float_as_uint(x0.x)), "r"(__float_as_uint(x0.y)),
                    "r"(__float_as_uint(x0.z)), "r"(__float_as_uint(x0.w)),
                    "r"(__float_as_uint(x1.x)), "r"(__float_as_uint(x1.y)),
                    "r"(__float_as_uint(x1.z)), "r"(__float_as_uint(x1.w))
                 : "memory");
}

// Warp-autonomous staging: each warp owns 64 items and a private 2304B smem
// slab; computes, stages (stride-9 STS, conflict-free), __syncwarp()s, drains
// its own slab with LDS.128 pairs + 256-bit STG. No block barrier.
// 512 items/block (8 warps x 64), 2 items/thread.
__global__ __launch_bounds__(256)
void homography_expm_kernel(const float* __restrict__ v,
                            float* __restrict__ o,
                            int n)
{
    __shared__ __align__(32) float s[8][576];   // per-warp slab: 64 items * 9 floats

    const unsigned tid  = threadIdx.x;
    const unsigned wid  = tid >> 5;
    const unsigned lane = tid & 31u;

    const unsigned gbase = blockIdx.x * 512u + wid * 64u;   // warp's first item
    const unsigned iA = gbase + lane;
    const unsigned iB = gbase + 32u + lane;

    float* sw = s[wid];

    if (iB < (unsigned)n) {
        // fast path: both items valid — two 256-bit loads, front-batched
        float vA[8], vB[8];
        ldg256_cs(v + iA * 8u, vA);
        ldg256_cs(v + iB * 8u, vB);

        float HA[9];
        expm3x3_ch(vA, HA);
#pragma unroll
        for (int k = 0; k < 9; k++) sw[lane * 9u + k] = HA[k];

        float HB[9];
        expm3x3_ch(vB, HB);
#pragma unroll
        for (int k = 0; k < 9; k++) sw[(32u + lane) * 9u + k] = HB[k];
    } else if (iA < (unsigned)n) {
        float vA[8];
        ldg256_cs(v + iA * 8u, vA);
        float HA[9];
        expm3x3_ch(vA, HA);
#pragma unroll
        for (int k = 0; k < 9; k++) sw[lane * 9u + k] = HA[k];
    }
    __syncwarp();

    if (gbase + 64u <= (unsigned)n) {
        // full warp group: drain 2304B slab as 72 x 32B chunks (256-bit stores)
        // rounds 0,1: chunks lane+0 / lane+32 ; round 2: lanes 0-7, chunks 64-71
        const float4* sf = reinterpret_cast<const float4*>(sw);
        float* dst = o + gbase * 9u;            // 32B-aligned (gbase % 64 == 0)
#pragma unroll
        for (unsigned i = 0; i < 2; i++) {
            const unsigned c = lane + 32u * i;
            stg256_cs(dst + 8u * c, sf[2u * c], sf[2u * c + 1u]);
        }
        if (lane < 8u) {
            const unsigned c = 64u + lane;
            stg256_cs(dst + 8u * c, sf[2u * c], sf[2u * c + 1u]);
        }
    } else if (gbase < (unsigned)n) {
        // tail group: guarded coalesced scalar copy
        const unsigned total = ((unsigned)n - gbase) * 9u;
        float* dst = o + gbase * 9u;
        for (unsigned idx = lane; idx < total; idx += 32u) dst[idx] = sw[idx];
    }
}

extern "C" void kernel_launch(void* const* d_in, const int* in_sizes, int n_in,
                              void* d_out, int out_size)
{
    const float* v = (const float*)d_in[0];
    float* o = (float*)d_out;
    const int n = in_sizes[0] / 8;
    const int grid = (n + 511) / 512;
    homography_expm_kernel<<<grid, 256>>>(v, o, n);
}